// round 8
// baseline (speedup 1.0000x reference)
#include <cuda_runtime.h>
#include <cuda_bf16.h>
#include <cuda_fp8.h>
#include <cstdint>

// ---------------- problem dims ----------------
#define M_TOTAL 8192
#define N_TOTAL 4096
#define K_TOTAL 4096
#define FP8_MAX_F 448.0f

// ---------------- GEMM tiling (fp8 operands) ----------------
#define TILE_M 128
#define TILE_N 128
#define KC 128                      // fp8 per K-stage => 128 bytes per row (SW128 atom)
#define STAGES 3
#define KITERS (K_TOTAL / KC)       // 32
#define GEMM_THREADS 256

// SMEM layout: per stage A tile (128 rows x 128B) + B tile (128 rows x 128B)
#define A_BYTES (TILE_M * 128)              // 16384
#define B_BYTES (TILE_N * 128)              // 16384
#define STAGE_BYTES (A_BYTES + B_BYTES)     // 32768
#define A_OFF(s) ((s) * STAGE_BYTES)
#define B_OFF(s) (A_OFF(s) + A_BYTES)
#define SMEM_TOTAL (STAGES * STAGE_BYTES)   // 98304

// ---------------- device scratch (__device__ globals: allocation-free rule) ----------------
__device__ unsigned g_absmax_bits[2];                      // [0]=x, [1]=W
__device__ float g_scales[3];                              // x_scale, w_scale, product
__device__ uint8_t g_xq[(size_t)M_TOTAL * K_TOTAL];        // 32 MB fp8 bytes
__device__ uint8_t g_wq[(size_t)N_TOTAL * K_TOTAL];        // 16 MB fp8 bytes

// ---------------- helpers ----------------
__device__ __forceinline__ uint32_t smem_u32(const void* p) {
    uint32_t a;
    asm("{ .reg .u64 t; cvta.to.shared.u64 t, %1; cvt.u32.u64 %0, t; }" : "=r"(a) : "l"(p));
    return a;
}

#define SWZ(o) ((o) ^ (((o) >> 3) & 0x70))

__device__ __forceinline__ void cp16(uint32_t dst, const void* src) {
    asm volatile("cp.async.cg.shared.global [%0], [%1], 16;" :: "r"(dst), "l"(src));
}
__device__ __forceinline__ void cp_commit() {
    asm volatile("cp.async.commit_group;" ::: "memory");
}
template <int N>
__device__ __forceinline__ void cp_wait() {
    asm volatile("cp.async.wait_group %0;" :: "n"(N) : "memory");
}

__device__ __forceinline__ void ldsm_x4(uint32_t* r, uint32_t addr) {
    asm volatile("ldmatrix.sync.aligned.m8n8.x4.shared.b16 {%0,%1,%2,%3}, [%4];"
                 : "=r"(r[0]), "=r"(r[1]), "=r"(r[2]), "=r"(r[3]) : "r"(addr));
}
__device__ __forceinline__ void ldsm_x2(uint32_t* r, uint32_t addr) {
    asm volatile("ldmatrix.sync.aligned.m8n8.x2.shared.b16 {%0,%1}, [%2];"
                 : "=r"(r[0]), "=r"(r[1]) : "r"(addr));
}

// fp8 e4m3 MMA: m16n8k32, fp32 accumulate (sm_89-base PTX feature)
__device__ __forceinline__ void mma_fp8(float* c, const uint32_t* a, const uint32_t* b) {
    asm volatile(
        "mma.sync.aligned.m16n8k32.row.col.f32.e4m3.e4m3.f32 "
        "{%0,%1,%2,%3}, {%4,%5,%6,%7}, {%8,%9}, {%0,%1,%2,%3};"
        : "+f"(c[0]), "+f"(c[1]), "+f"(c[2]), "+f"(c[3])
        : "r"(a[0]), "r"(a[1]), "r"(a[2]), "r"(a[3]), "r"(b[0]), "r"(b[1]));
}

// ---------------- preprocessing kernels ----------------
__global__ void reset_kernel() {
    g_absmax_bits[0] = 0u;
    g_absmax_bits[1] = 0u;
}

__global__ void absmax_kernel(const float4* __restrict__ p, int n4, int slot) {
    float m = 0.f;
    for (int i = blockIdx.x * blockDim.x + threadIdx.x; i < n4; i += gridDim.x * blockDim.x) {
        float4 v = p[i];
        m = fmaxf(m, fmaxf(fmaxf(fabsf(v.x), fabsf(v.y)), fmaxf(fabsf(v.z), fabsf(v.w))));
    }
#pragma unroll
    for (int o = 16; o; o >>= 1) m = fmaxf(m, __shfl_xor_sync(0xFFFFFFFFu, m, o));
    if ((threadIdx.x & 31) == 0) atomicMax(&g_absmax_bits[slot], __float_as_uint(m));
}

__global__ void scales_kernel() {
    float xm = __uint_as_float(g_absmax_bits[0]);
    float wm = __uint_as_float(g_absmax_bits[1]);
    float xs = xm > 0.f ? __fdiv_rn(xm, FP8_MAX_F) : 1.0f;   // matches jnp.where guard
    float ws = __fdiv_rn(wm, FP8_MAX_F);
    g_scales[0] = xs;
    g_scales[1] = ws;
    g_scales[2] = xs * ws;
}

__device__ __forceinline__ uint8_t quant1(float v, float s) {
    float d = __fdiv_rn(v, s);               // RNE f32 division, same as reference
    __nv_fp8_e4m3 q(d);                      // satfinite RNE -> e4m3
    return *reinterpret_cast<uint8_t*>(&q);
}

__global__ void quant_kernel(const float4* __restrict__ src, int n4, int which) {
    uint8_t* dst = (which == 0) ? g_xq : g_wq;
    float s = g_scales[which];
    for (int i = blockIdx.x * blockDim.x + threadIdx.x; i < n4; i += gridDim.x * blockDim.x) {
        float4 v = src[i];
        uint32_t pk = (uint32_t)quant1(v.x, s)
                    | ((uint32_t)quant1(v.y, s) << 8)
                    | ((uint32_t)quant1(v.z, s) << 16)
                    | ((uint32_t)quant1(v.w, s) << 24);
        reinterpret_cast<uint32_t*>(dst)[i] = pk;
    }
}

// ---------------- GEMM kernel (mma.sync e4m3, sm_103-base ISA) ----------------
__device__ __forceinline__ void load_stage(uint32_t smem_base, int s, int kit, int m0, int n0, int tid) {
    int k0 = kit * KC;   // byte offset along K (1 byte per element)
    {
        uint32_t base = smem_base + A_OFF(s);
        const uint8_t* gA = g_xq + (size_t)m0 * K_TOTAL + k0;
#pragma unroll
        for (int q = tid; q < (TILE_M * 8); q += GEMM_THREADS) {   // 1024 16B chunks
            int r = q >> 3, c = q & 7;
            uint32_t off = (uint32_t)(r * 128 + c * 16);
            cp16(base + SWZ(off), gA + (size_t)r * K_TOTAL + c * 16);
        }
    }
    {
        uint32_t base = smem_base + B_OFF(s);
        const uint8_t* gB = g_wq + (size_t)n0 * K_TOTAL + k0;
#pragma unroll
        for (int q = tid; q < (TILE_N * 8); q += GEMM_THREADS) {   // 1024 16B chunks
            int r = q >> 3, c = q & 7;
            uint32_t off = (uint32_t)(r * 128 + c * 16);
            cp16(base + SWZ(off), gB + (size_t)r * K_TOTAL + c * 16);
        }
    }
}

__global__ void __launch_bounds__(GEMM_THREADS, 2)
gemm_kernel(float* __restrict__ out, const float* __restrict__ bias) {
    extern __shared__ char smem[];
    uint32_t smem_base = smem_u32(smem);
    int tid = threadIdx.x;
    int wid = tid >> 5, lane = tid & 31;

    // supertile rasterization: 8 M-blocks tall stripes across all N-blocks
    const int tiles_n = N_TOTAL / TILE_N;   // 32
    const int SUPER = 8;
    int id = blockIdx.x;
    int sid = id / (SUPER * tiles_n);
    int within = id % (SUPER * tiles_n);
    int bm = sid * SUPER + (within % SUPER);
    int bn = within / SUPER;
    int m0 = bm * TILE_M, n0 = bn * TILE_N;

    // warp tiling: 4 warps along M (32 rows each), 2 along N (64 cols each)
    int wm = (wid >> 1) * 32;
    int wn = (wid & 1) * 64;

    float c[2][8][4];
#pragma unroll
    for (int i = 0; i < 2; ++i)
#pragma unroll
        for (int j = 0; j < 8; ++j)
#pragma unroll
            for (int v = 0; v < 4; ++v) c[i][j][v] = 0.f;

    // ldmatrix lane-address components. For 8-bit mma the fragment register =
    // 4 consecutive K-bytes of one row, which is exactly one ldmatrix.b16
    // register when the fp8 tile is viewed as halfwords => identical formulas
    // to the bf16 path, with "chunk" = 16-byte unit along K.
    uint32_t a_row = (uint32_t)(wm + (lane & 7) + ((lane >> 3) & 1) * 8);
    uint32_t a_chunk_lane = (uint32_t)(lane >> 4);
    int l16 = lane & 15;
    uint32_t b_row = (uint32_t)(wn + (l16 & 7));
    uint32_t b_chunk_lane = (uint32_t)(l16 >> 3);

    // prologue: fill STAGES-1 stages
#pragma unroll
    for (int s = 0; s < STAGES - 1; ++s) {
        load_stage(smem_base, s, s, m0, n0, tid);
        cp_commit();
    }

    for (int it = 0; it < KITERS; ++it) {
        int s = it % STAGES;
        cp_wait<STAGES - 2>();
        __syncthreads();

        int nit = it + STAGES - 1;
        if (nit < KITERS) load_stage(smem_base, nit % STAGES, nit, m0, n0, tid);
        cp_commit();

        uint32_t aBase = smem_base + A_OFF(s);
        uint32_t bBase = smem_base + B_OFF(s);

#pragma unroll
        for (int kk = 0; kk < KC / 32; ++kk) {            // 4 k32 steps per stage
            uint32_t a[2][4];
#pragma unroll
            for (int i = 0; i < 2; ++i) {
                uint32_t row = a_row + i * 16;
                uint32_t chunk = 2 * kk + a_chunk_lane;   // 2 x 16B chunks per k32
                ldsm_x4(a[i], aBase + SWZ(row * 128 + chunk * 16));
            }
            uint32_t b[8][2];
#pragma unroll
            for (int j = 0; j < 8; ++j) {
                uint32_t row = b_row + j * 8;
                uint32_t chunk = 2 * kk + b_chunk_lane;
                ldsm_x2(b[j], bBase + SWZ(row * 128 + chunk * 16));
            }
#pragma unroll
            for (int i = 0; i < 2; ++i)
#pragma unroll
                for (int j = 0; j < 8; ++j)
                    mma_fp8(c[i][j], a[i], b[j]);
        }
    }

    // epilogue: scale + bias, f32 out (C layout of m16n8k32 == m16n8k16)
    float scale = g_scales[2];
    int g = lane >> 2, t = lane & 3;
#pragma unroll
    for (int i = 0; i < 2; ++i) {
        int r0 = m0 + wm + i * 16 + g;
        float* orow0 = out + (size_t)r0 * N_TOTAL;
        float* orow1 = orow0 + (size_t)8 * N_TOTAL;
#pragma unroll
        for (int j = 0; j < 8; ++j) {
            int col = n0 + wn + j * 8 + t * 2;
            float b0 = bias[col], b1 = bias[col + 1];
            float2 v0 = make_float2(c[i][j][0] * scale + b0, c[i][j][1] * scale + b1);
            float2 v1 = make_float2(c[i][j][2] * scale + b0, c[i][j][3] * scale + b1);
            *reinterpret_cast<float2*>(orow0 + col) = v0;
            *reinterpret_cast<float2*>(orow1 + col) = v1;
        }
    }
}

// ---------------- launch ----------------
extern "C" void kernel_launch(void* const* d_in, const int* in_sizes, int n_in,
                              void* d_out, int out_size) {
    const float *x = nullptr, *W = nullptr, *bias = nullptr;
    for (int i = 0; i < n_in; ++i) {
        if (in_sizes[i] == N_TOTAL) bias = (const float*)d_in[i];
        else if (in_sizes[i] == M_TOTAL * K_TOTAL) x = (const float*)d_in[i];
        else W = (const float*)d_in[i];
    }
    float* out = (float*)d_out;

    reset_kernel<<<1, 1>>>();
    absmax_kernel<<<1184, 256>>>((const float4*)x, (M_TOTAL * K_TOTAL) / 4, 0);
    absmax_kernel<<<1184, 256>>>((const float4*)W, (N_TOTAL * K_TOTAL) / 4, 1);
    scales_kernel<<<1, 1>>>();
    quant_kernel<<<1184, 256>>>((const float4*)x, (M_TOTAL * K_TOTAL) / 4, 0);
    quant_kernel<<<1184, 256>>>((const float4*)W, (N_TOTAL * K_TOTAL) / 4, 1);

    cudaFuncSetAttribute(gemm_kernel, cudaFuncAttributeMaxDynamicSharedMemorySize, SMEM_TOTAL);
    int grid = (M_TOTAL / TILE_M) * (N_TOTAL / TILE_N);   // 64 * 32 = 2048
    gemm_kernel<<<grid, GEMM_THREADS, SMEM_TOTAL>>>(out, bias);
}

// round 14
// speedup vs baseline: 1.2997x; 1.2997x over previous
#include <cuda_runtime.h>
#include <cuda_bf16.h>
#include <cuda_fp8.h>
#include <cstdint>

// ---------------- problem dims ----------------
#define M_TOTAL 8192
#define N_TOTAL 4096
#define K_TOTAL 4096
#define FP8_MAX_F 448.0f

// ---------------- GEMM tiling ----------------
#define TILE_M 128
#define TILE_N 128
#define KC 64                       // bf16 per K-stage => 128 bytes per row
#define STAGES 3
#define KITERS (K_TOTAL / KC)       // 64
#define GEMM_THREADS 256

#define A_BYTES (TILE_M * 128)              // 16384
#define B_BYTES (TILE_N * 128)              // 16384
#define STAGE_BYTES (A_BYTES + B_BYTES)     // 32768
#define A_OFF(s) ((s) * STAGE_BYTES)
#define B_OFF(s) (A_OFF(s) + A_BYTES)
#define SMEM_TOTAL (STAGES * STAGE_BYTES)   // 98304

// absmax/quant grids: x has 8M float4, W has 4M float4 -> 2:1 block split
#define PRE_BLOCKS 1184
#define X_BLOCKS 790                       // blocks [0,790) -> x, [790,1184) -> W
#define X_N4 ((M_TOTAL * K_TOTAL) / 4)
#define W_N4 ((N_TOTAL * K_TOTAL) / 4)

// ---------------- device scratch ----------------
__device__ unsigned g_absmax_bits[2];                          // [0]=x, [1]=W
__device__ __nv_bfloat16 g_xq[(size_t)M_TOTAL * K_TOTAL];      // 64 MB
__device__ __nv_bfloat16 g_wq[(size_t)N_TOTAL * K_TOTAL];      // 32 MB

// ---------------- helpers ----------------
__device__ __forceinline__ uint32_t smem_u32(const void* p) {
    uint32_t a;
    asm("{ .reg .u64 t; cvta.to.shared.u64 t, %1; cvt.u32.u64 %0, t; }" : "=r"(a) : "l"(p));
    return a;
}

#define SWZ(o) ((o) ^ (((o) >> 3) & 0x70))

__device__ __forceinline__ void cp16(uint32_t dst, const void* src) {
    asm volatile("cp.async.cg.shared.global [%0], [%1], 16;" :: "r"(dst), "l"(src));
}
__device__ __forceinline__ void cp_commit() {
    asm volatile("cp.async.commit_group;" ::: "memory");
}
template <int N>
__device__ __forceinline__ void cp_wait() {
    asm volatile("cp.async.wait_group %0;" :: "n"(N) : "memory");
}

__device__ __forceinline__ void ldsm_x4(uint32_t* r, uint32_t addr) {
    asm volatile("ldmatrix.sync.aligned.m8n8.x4.shared.b16 {%0,%1,%2,%3}, [%4];"
                 : "=r"(r[0]), "=r"(r[1]), "=r"(r[2]), "=r"(r[3]) : "r"(addr));
}

__device__ __forceinline__ void mma_bf16(float* c, const uint32_t* a, const uint32_t* b) {
    asm volatile(
        "mma.sync.aligned.m16n8k16.row.col.f32.bf16.bf16.f32 "
        "{%0,%1,%2,%3}, {%4,%5,%6,%7}, {%8,%9}, {%0,%1,%2,%3};"
        : "+f"(c[0]), "+f"(c[1]), "+f"(c[2]), "+f"(c[3])
        : "r"(a[0]), "r"(a[1]), "r"(a[2]), "r"(a[3]), "r"(b[0]), "r"(b[1]));
}

__device__ __forceinline__ float compute_scale(int slot) {
    float m = __uint_as_float(g_absmax_bits[slot]);
    float s = __fdiv_rn(m, FP8_MAX_F);               // RNE f32 division, matches jnp
    if (slot == 0 && !(m > 0.f)) s = 1.0f;           // jnp.where guard (x only)
    return s;
}

// ---------------- preprocessing ----------------
__global__ void reset_kernel() {
    g_absmax_bits[0] = 0u;
    g_absmax_bits[1] = 0u;
}

// launch index 1: both tensors in one kernel (block-partitioned)
__global__ void absmax_both_kernel(const float4* __restrict__ x, const float4* __restrict__ w) {
    int slot = (blockIdx.x >= X_BLOCKS) ? 1 : 0;
    const float4* p = slot ? w : x;
    int n4 = slot ? W_N4 : X_N4;
    int b0 = slot ? X_BLOCKS : 0;
    int nb = slot ? (PRE_BLOCKS - X_BLOCKS) : X_BLOCKS;
    float m = 0.f;
    for (int i = (blockIdx.x - b0) * blockDim.x + threadIdx.x; i < n4; i += nb * blockDim.x) {
        float4 v = p[i];
        m = fmaxf(m, fmaxf(fmaxf(fabsf(v.x), fabsf(v.y)), fmaxf(fabsf(v.z), fabsf(v.w))));
    }
#pragma unroll
    for (int o = 16; o; o >>= 1) m = fmaxf(m, __shfl_xor_sync(0xFFFFFFFFu, m, o));
    if ((threadIdx.x & 31) == 0) atomicMax(&g_absmax_bits[slot], __float_as_uint(m));
}

__device__ __forceinline__ __nv_bfloat16 quant1(float v, float s) {
    float d = __fdiv_rn(v, s);               // RNE f32 division, same as reference
    __nv_fp8_e4m3 q(d);                      // satfinite RNE -> e4m3
    return __float2bfloat16(float(q));       // exact: e4m3 is a subset of bf16
}

// launch index 2: quantize both tensors; scale computed inline from absmax bits
__global__ void quant_both_kernel(const float4* __restrict__ x, const float4* __restrict__ w) {
    int slot = (blockIdx.x >= X_BLOCKS) ? 1 : 0;
    const float4* src = slot ? w : x;
    uint2* dst = slot ? (uint2*)g_wq : (uint2*)g_xq;
    int n4 = slot ? W_N4 : X_N4;
    int b0 = slot ? X_BLOCKS : 0;
    int nb = slot ? (PRE_BLOCKS - X_BLOCKS) : X_BLOCKS;
    float s = compute_scale(slot);
    for (int i = (blockIdx.x - b0) * blockDim.x + threadIdx.x; i < n4; i += nb * blockDim.x) {
        float4 v = src[i];
        union { __nv_bfloat16 h[4]; uint2 u; } pk;
        pk.h[0] = quant1(v.x, s);
        pk.h[1] = quant1(v.y, s);
        pk.h[2] = quant1(v.z, s);
        pk.h[3] = quant1(v.w, s);
        dst[i] = pk.u;
    }
}

// ---------------- GEMM kernel (mma.sync bf16) ----------------
__device__ __forceinline__ void load_stage(uint32_t smem_base, int s, int kit, int m0, int n0, int tid) {
    int k0 = kit * KC;
    {
        uint32_t base = smem_base + A_OFF(s);
        const __nv_bfloat16* gA = g_xq + (size_t)m0 * K_TOTAL + k0;
#pragma unroll
        for (int q = tid; q < (TILE_M * 8); q += GEMM_THREADS) {   // 1024 16B chunks
            int r = q >> 3, c = q & 7;
            uint32_t off = (uint32_t)(r * 128 + c * 16);
            cp16(base + SWZ(off), gA + (size_t)r * K_TOTAL + c * 8);
        }
    }
    {
        uint32_t base = smem_base + B_OFF(s);
        const __nv_bfloat16* gB = g_wq + (size_t)n0 * K_TOTAL + k0;
#pragma unroll
        for (int q = tid; q < (TILE_N * 8); q += GEMM_THREADS) {   // 1024 16B chunks
            int r = q >> 3, c = q & 7;
            uint32_t off = (uint32_t)(r * 128 + c * 16);
            cp16(base + SWZ(off), gB + (size_t)r * K_TOTAL + c * 8);
        }
    }
}

__global__ void __launch_bounds__(GEMM_THREADS, 2)
gemm_kernel(float* __restrict__ out, const float* __restrict__ bias) {
    extern __shared__ char smem[];
    uint32_t smem_base = smem_u32(smem);
    int tid = threadIdx.x;
    int wid = tid >> 5, lane = tid & 31;

    // supertile rasterization: 8 M-blocks tall stripes across all N-blocks
    const int tiles_n = N_TOTAL / TILE_N;   // 32
    const int SUPER = 8;
    int id = blockIdx.x;
    int sid = id / (SUPER * tiles_n);
    int within = id % (SUPER * tiles_n);
    int bm = sid * SUPER + (within % SUPER);
    int bn = within / SUPER;
    int m0 = bm * TILE_M, n0 = bn * TILE_N;

    // warp tiling: 4 warps along M (32 rows each), 2 along N (64 cols each)
    int wm = (wid >> 1) * 32;
    int wn = (wid & 1) * 64;

    float c[2][8][4];
#pragma unroll
    for (int i = 0; i < 2; ++i)
#pragma unroll
        for (int j = 0; j < 8; ++j)
#pragma unroll
            for (int v = 0; v < 4; ++v) c[i][j][v] = 0.f;

    // A ldmatrix lane addressing (x4: 16 rows x k16)
    uint32_t a_row = (uint32_t)(wm + (lane & 7) + ((lane >> 3) & 1) * 8);
    uint32_t a_chunk_lane = (uint32_t)(lane >> 4);
    // B ldmatrix x4 pairing: matrices {0,1} -> j block (k-lo, k-hi),
    //                        matrices {2,3} -> j+1 block (k-lo, k-hi)
    // lane -> row = wn + ((lane>>4)<<3) + (lane&7) + 16p, chunk = 2kk + ((lane>>3)&1)
    uint32_t b_row4 = (uint32_t)(wn + ((lane >> 4) << 3) + (lane & 7));
    uint32_t b_chunk4 = (uint32_t)((lane >> 3) & 1);

    // prologue: fill STAGES-1 stages
#pragma unroll
    for (int s = 0; s < STAGES - 1; ++s) {
        load_stage(smem_base, s, s, m0, n0, tid);
        cp_commit();
    }

    for (int it = 0; it < KITERS; ++it) {
        int s = it % STAGES;
        cp_wait<STAGES - 2>();
        __syncthreads();

        int nit = it + STAGES - 1;
        if (nit < KITERS) load_stage(smem_base, nit % STAGES, nit, m0, n0, tid);
        cp_commit();

        uint32_t aBase = smem_base + A_OFF(s);
        uint32_t bBase = smem_base + B_OFF(s);

#pragma unroll
        for (int kk = 0; kk < KC / 16; ++kk) {            // 4 k16 steps
            uint32_t a[2][4];
#pragma unroll
            for (int i = 0; i < 2; ++i) {
                uint32_t row = a_row + i * 16;
                uint32_t chunk = 2 * kk + a_chunk_lane;
                ldsm_x4(a[i], aBase + SWZ(row * 128 + chunk * 16));
            }
            uint32_t b[8][2];                              // b[2p],b[2p+1] contiguous
#pragma unroll
            for (int p = 0; p < 4; ++p) {
                uint32_t row = b_row4 + (uint32_t)(p * 16);
                uint32_t chunk = 2 * kk + b_chunk4;
                ldsm_x4(&b[2 * p][0], bBase + SWZ(row * 128 + chunk * 16));
            }
#pragma unroll
            for (int i = 0; i < 2; ++i)
#pragma unroll
                for (int j = 0; j < 8; ++j)
                    mma_bf16(c[i][j], a[i], b[j]);
        }
    }

    // epilogue: scale + bias, f32 out; scale derived inline from absmax bits
    float scale = compute_scale(0) * compute_scale(1);
    int g = lane >> 2, t = lane & 3;
#pragma unroll
    for (int i = 0; i < 2; ++i) {
        int r0 = m0 + wm + i * 16 + g;
        float* orow0 = out + (size_t)r0 * N_TOTAL;
        float* orow1 = orow0 + (size_t)8 * N_TOTAL;
#pragma unroll
        for (int j = 0; j < 8; ++j) {
            int col = n0 + wn + j * 8 + t * 2;
            float b0 = bias[col], b1 = bias[col + 1];
            float2 v0 = make_float2(c[i][j][0] * scale + b0, c[i][j][1] * scale + b1);
            float2 v1 = make_float2(c[i][j][2] * scale + b0, c[i][j][3] * scale + b1);
            *reinterpret_cast<float2*>(orow0 + col) = v0;
            *reinterpret_cast<float2*>(orow1 + col) = v1;
        }
    }
}

// ---------------- launch (GEMM is launch index 3 -> ncu capture slot) ----------------
extern "C" void kernel_launch(void* const* d_in, const int* in_sizes, int n_in,
                              void* d_out, int out_size) {
    const float *x = nullptr, *W = nullptr, *bias = nullptr;
    for (int i = 0; i < n_in; ++i) {
        if (in_sizes[i] == N_TOTAL) bias = (const float*)d_in[i];
        else if (in_sizes[i] == M_TOTAL * K_TOTAL) x = (const float*)d_in[i];
        else W = (const float*)d_in[i];
    }
    float* out = (float*)d_out;

    reset_kernel<<<1, 1>>>();                                               // 0
    absmax_both_kernel<<<PRE_BLOCKS, 256>>>((const float4*)x, (const float4*)W); // 1
    quant_both_kernel<<<PRE_BLOCKS, 256>>>((const float4*)x, (const float4*)W);  // 2

    cudaFuncSetAttribute(gemm_kernel, cudaFuncAttributeMaxDynamicSharedMemorySize, SMEM_TOTAL);
    int grid = (M_TOTAL / TILE_M) * (N_TOTAL / TILE_N);   // 2048
    gemm_kernel<<<grid, GEMM_THREADS, SMEM_TOTAL>>>(out, bias);             // 3
}